// round 8
// baseline (speedup 1.0000x reference)
#include <cuda_runtime.h>
#include <cuda_bf16.h>
#include <cstdint>

#define BB   4096
#define OBSD 512
#define ACTD 64
#define NT   10
#define NE   16
#define DREP 1024
#define DH   1024
#define DKK  512
#define XDIM 576   // OBSD+ACTD
#define SDIM 522   // OBSD+NT

// ---------------- scratch (device globals; no allocs allowed) ----------------
__device__ __align__(256) float g_x[BB * XDIM];
__device__ int   g_task[BB];
__device__ float g_wq[NE * NT * DH];
__device__ float g_qb[NE * NT];
__device__ __align__(256) float g_h0[BB * DREP];
__device__ __align__(256) float g_rep[BB * DREP];
__device__ float g_logits[BB * NE];
__device__ float g_attn[BB * NE];
__device__ __align__(256) float g_gv[(size_t)BB * NE * DH];   // attn-scaled hv, [b][e*DH+h]
__device__ __align__(256) float g_tin[BB * DKK];
__device__ __align__(256) float g_t1[BB * 512];
__device__ __align__(256) float g_t2[BB * 256];
__device__ float g_loss;

// ---------------- helpers ----------------
__device__ __forceinline__ float rna_tf32(float x) {
    uint32_t u;
    asm("cvt.rna.tf32.f32 %0, %1;" : "=r"(u) : "f"(x));
    return __uint_as_float(u);
}
__device__ __forceinline__ uint32_t rna_tf32_bits(float x) {
    uint32_t u;
    asm("cvt.rna.tf32.f32 %0, %1;" : "=r"(u) : "f"(x));
    return u;
}

__device__ __forceinline__ void cpa16(void* smem, const void* gsrc) {
    uint32_t sa = (uint32_t)__cvta_generic_to_shared(smem);
    asm volatile("cp.async.cg.shared.global [%0], [%1], 16;\n" :: "r"(sa), "l"(gsrc));
}
__device__ __forceinline__ void cpa_commit() { asm volatile("cp.async.commit_group;\n" ::); }

__device__ __forceinline__ void mma_tf32(float* c, const uint32_t* a, const uint32_t* b) {
    asm volatile(
        "mma.sync.aligned.m16n8k8.row.col.f32.tf32.tf32.f32 "
        "{%0,%1,%2,%3}, {%4,%5,%6,%7}, {%8,%9}, {%0,%1,%2,%3};"
        : "+f"(c[0]), "+f"(c[1]), "+f"(c[2]), "+f"(c[3])
        : "r"(a[0]), "r"(a[1]), "r"(a[2]), "r"(a[3]), "r"(b[0]), "r"(b[1]));
}

// ---------------- small kernels ----------------
__global__ void prep_kernel(const float* __restrict__ state, const float* __restrict__ act) {
    int b = blockIdx.x;
    const float* srow = state + (size_t)b * SDIM;
    float* xrow = g_x + (size_t)b * XDIM;
    for (int i = threadIdx.x; i < XDIM; i += blockDim.x) {
        float v = (i < OBSD) ? srow[i] : act[(size_t)b * ACTD + (i - OBSD)];
        xrow[i] = rna_tf32(v);
    }
    if (threadIdx.x == 0) {
        float best = srow[OBSD]; int bi = 0;
        for (int t = 1; t < NT; t++) { float v = srow[OBSD + t]; if (v > best) { best = v; bi = t; } }
        g_task[b] = bi;
    }
}

// wq[e,t,h] = sum_k Wk1[e,h,k] * tanh(emb[t,k]);  qb[e,t] = sum_k bk1[e,k]*tanh(emb[t,k])
__global__ void wq_kernel(const float* __restrict__ Wk1, const float* __restrict__ bk1,
                          const float* __restrict__ emb) {
    int e = blockIdx.x, t = blockIdx.y;
    __shared__ float q[DKK];
    for (int k = threadIdx.x; k < DKK; k += blockDim.x) q[k] = tanhf(emb[t * DKK + k]);
    __syncthreads();
    const float* Wb = Wk1 + (size_t)e * DH * DKK;
    for (int h = threadIdx.x; h < DH; h += blockDim.x) {
        const float* wr = Wb + (size_t)h * DKK;
        float s = 0.f;
        for (int k = 0; k < DKK; k++) s += wr[k] * q[k];
        g_wq[((size_t)e * NT + t) * DH + h] = s;
    }
    if (threadIdx.x == 0) {
        float s = 0.f;
        const float* br = bk1 + (size_t)e * DKK;
        for (int k = 0; k < DKK; k++) s += br[k] * q[k];
        g_qb[e * NT + t] = s;
    }
}

__global__ void initlogits_kernel() {
    int i = blockIdx.x * blockDim.x + threadIdx.x;
    if (i < BB * NE) {
        int b = i >> 4, e = i & 15;
        g_logits[i] = g_qb[e * NT + g_task[b]];
    }
    if (i == 0) g_loss = 0.f;
}

__global__ void softmax_kernel() {
    int b = blockIdx.x * blockDim.x + threadIdx.x;  // grid exact: BB threads
    float l[NE];
    float mx = -1e30f;
#pragma unroll
    for (int e = 0; e < NE; e++) { l[e] = g_logits[b * NE + e]; mx = fmaxf(mx, l[e]); }
    float s = 0.f;
#pragma unroll
    for (int e = 0; e < NE; e++) { l[e] = expf(l[e] - mx); s += l[e]; }
    float inv = 1.f / s;
    float lp = 0.f;
#pragma unroll
    for (int e = 0; e < NE; e++) {
        float a = l[e] * inv;
        g_attn[b * NE + e] = a;
        float lg = logf(a + 1e-10f);
        lp += fminf(fmaxf(lg, -6.f), 0.f);
    }
#pragma unroll
    for (int o = 16; o > 0; o >>= 1) lp += __shfl_xor_sync(0xffffffffu, lp, o);
    __shared__ float red[8];
    if ((threadIdx.x & 31) == 0) red[threadIdx.x >> 5] = lp;
    __syncthreads();
    if (threadIdx.x == 0) {
        float sb = 0.f;
        for (int w = 0; w < (int)(blockDim.x >> 5); w++) sb += red[w];
        atomicAdd(&g_loss, sb);
    }
}

// tin = round_tf32( tin + sum_e attn[b,e]*bv1[e,k] )
__global__ void mixbias_kernel(const float* __restrict__ bv1) {
    int i = blockIdx.x * blockDim.x + threadIdx.x;
    if (i < BB * DKK) {
        int b = i >> 9, k = i & 511;
        float s = g_tin[i];
#pragma unroll
        for (int e = 0; e < NE; e++) s += g_attn[b * NE + e] * bv1[e * DKK + k];
        g_tin[i] = rna_tf32(s);
    }
}

__global__ void finalize_kernel(const float* __restrict__ Wt2, const float* __restrict__ bt2,
                                float* __restrict__ out, int out_size) {
    int wid = threadIdx.x >> 5, lane = threadIdx.x & 31;
    int b = blockIdx.x * 8 + wid;
    const float* row = g_t2 + (size_t)b * 256;
    float s = 0.f;
#pragma unroll
    for (int k = 0; k < 256; k += 32) s += row[k + lane] * Wt2[k + lane];
#pragma unroll
    for (int o = 16; o > 0; o >>= 1) s += __shfl_xor_sync(0xffffffffu, s, o);
    if (lane == 0) out[b] = s + bt2[0];
    if (blockIdx.x == 0 && threadIdx.x == 0 && out_size > BB)
        out[out_size - 1] = -(0.3f / (float)BB) * g_loss;
}

// ---------------- tf32 tensor-core GEMM ----------------
// C(M x N) = epi( A(M x K) @ B(K x N) + bias ). A is tf32-pre-rounded by its
// producer; B is RAW weights, rounded to tf32 in the register fragment path.
// Tile 128x128x16, 8 warps (2x4), warp tile 64x32, mma m16n8k8.
// EPI: 0 raw store, 1 relu+round, 2 round, 3 fused-logit (no C), 4 relu*attn+round, 5 relu
#define BM 128
#define BN 128
#define BKT 16
#define ASTR (BKT + 4)   // 20: conflict-free A-frag loads
#define BSTR (BN + 8)    // 136: conflict-free B-frag loads

template <int EPI>
__global__ void __launch_bounds__(256) gemm_tf32(
    const float* __restrict__ A, int lda,
    const float* __restrict__ B, int ldb, long long sB,
    float* __restrict__ C, int ldc, long long sC,
    const float* __restrict__ bias, int sBias,
    int K)
{
    __shared__ float As[2][BM][ASTR];
    __shared__ float Bs[2][BKT][BSTR];

    const int e = blockIdx.z;
    const float* Bp = B + (size_t)e * (size_t)sB;
    const float* biasp = bias ? bias + (size_t)e * (size_t)sBias : nullptr;
    const int bm0 = blockIdx.y * BM, bn0 = blockIdx.x * BN;
    const int tid = threadIdx.x;
    const int wid = tid >> 5, lane = tid & 31;
    const int wm = wid >> 2, wn = wid & 3;  // 2 x 4 warp grid
    const int g = lane >> 2, t = lane & 3;

    const int am = tid >> 2, akq = tid & 3;   // A stage: rows am, am+64; quad akq
    const int bk = tid >> 5, bnq = tid & 31;  // B stage: rows bk, bk+8; quad bnq

    const int nk = K / BKT;

    auto loadStage = [&](int s, int kt) {
        int k0 = kt * BKT;
        cpa16(&As[s][am][akq * 4],      A + (size_t)(bm0 + am) * lda + k0 + akq * 4);
        cpa16(&As[s][am + 64][akq * 4], A + (size_t)(bm0 + am + 64) * lda + k0 + akq * 4);
        cpa16(&Bs[s][bk][bnq * 4],      Bp + (size_t)(k0 + bk) * ldb + bn0 + bnq * 4);
        cpa16(&Bs[s][bk + 8][bnq * 4],  Bp + (size_t)(k0 + bk + 8) * ldb + bn0 + bnq * 4);
        cpa_commit();
    };

    float acc[4][4][4];
#pragma unroll
    for (int a = 0; a < 4; a++)
#pragma unroll
        for (int b2 = 0; b2 < 4; b2++)
#pragma unroll
            for (int c2 = 0; c2 < 4; c2++) acc[a][b2][c2] = 0.f;

    loadStage(0, 0);
    if (nk > 1) {
        loadStage(1, 1);
        asm volatile("cp.async.wait_group 1;\n" ::);
    } else {
        asm volatile("cp.async.wait_group 0;\n" ::);
    }
    __syncthreads();

    for (int kt = 0; kt < nk; ++kt) {
        int cur = kt & 1;
#pragma unroll
        for (int sub = 0; sub < 2; ++sub) {
            int kb = sub * 8;
            uint32_t af[4][4], bf[4][2];
#pragma unroll
            for (int mi = 0; mi < 4; mi++) {
                int r = wm * 64 + mi * 16 + g;
                af[mi][0] = __float_as_uint(As[cur][r][kb + t]);
                af[mi][1] = __float_as_uint(As[cur][r + 8][kb + t]);
                af[mi][2] = __float_as_uint(As[cur][r][kb + t + 4]);
                af[mi][3] = __float_as_uint(As[cur][r + 8][kb + t + 4]);
            }
#pragma unroll
            for (int ni = 0; ni < 4; ni++) {
                int c = wn * 32 + ni * 8 + g;
                bf[ni][0] = rna_tf32_bits(Bs[cur][kb + t][c]);
                bf[ni][1] = rna_tf32_bits(Bs[cur][kb + t + 4][c]);
            }
#pragma unroll
            for (int mi = 0; mi < 4; mi++)
#pragma unroll
                for (int ni = 0; ni < 4; ni++)
                    mma_tf32(acc[mi][ni], af[mi], bf[ni]);
        }
        __syncthreads();
        if (kt + 2 < nk) loadStage(cur, kt + 2);
        if (kt + 1 < nk) {
            if (kt + 2 < nk) { asm volatile("cp.async.wait_group 1;\n" ::); }
            else             { asm volatile("cp.async.wait_group 0;\n" ::); }
            __syncthreads();
        }
    }

    const int roff = bm0 + wm * 64;
    const int coff = bn0 + wn * 32;

    if (EPI == 3) {
        // logits[b,e] += sum_cols relu(acc+bias) * wq[e, task[b], col]
        float rs[4][2];
#pragma unroll
        for (int mi = 0; mi < 4; mi++) { rs[mi][0] = 0.f; rs[mi][1] = 0.f; }
#pragma unroll
        for (int mi = 0; mi < 4; mi++) {
            int r0 = roff + mi * 16 + g, r1 = r0 + 8;
            const float* w0 = g_wq + ((size_t)e * NT + g_task[r0]) * DH;
            const float* w1 = g_wq + ((size_t)e * NT + g_task[r1]) * DH;
#pragma unroll
            for (int ni = 0; ni < 4; ni++) {
                int c0 = coff + ni * 8 + 2 * t;
                float b0v = biasp[c0], b1v = biasp[c0 + 1];
                rs[mi][0] += fmaxf(acc[mi][ni][0] + b0v, 0.f) * w0[c0];
                rs[mi][0] += fmaxf(acc[mi][ni][1] + b1v, 0.f) * w0[c0 + 1];
                rs[mi][1] += fmaxf(acc[mi][ni][2] + b0v, 0.f) * w1[c0];
                rs[mi][1] += fmaxf(acc[mi][ni][3] + b1v, 0.f) * w1[c0 + 1];
            }
        }
#pragma unroll
        for (int mi = 0; mi < 4; mi++)
#pragma unroll
            for (int h = 0; h < 2; h++) {
                rs[mi][h] += __shfl_xor_sync(0xffffffffu, rs[mi][h], 1);
                rs[mi][h] += __shfl_xor_sync(0xffffffffu, rs[mi][h], 2);
            }
        if (t == 0) {
#pragma unroll
            for (int mi = 0; mi < 4; mi++) {
                int r0 = roff + mi * 16 + g;
                atomicAdd(&g_logits[(size_t)r0 * NE + e], rs[mi][0]);
                atomicAdd(&g_logits[(size_t)(r0 + 8) * NE + e], rs[mi][1]);
            }
        }
    } else {
        float* Cp = C + (size_t)e * (size_t)sC;
#pragma unroll
        for (int mi = 0; mi < 4; mi++) {
            int r0 = roff + mi * 16 + g, r1 = r0 + 8;
            float s0 = 1.f, s1 = 1.f;
            if (EPI == 4) { s0 = g_attn[(size_t)r0 * NE + e]; s1 = g_attn[(size_t)r1 * NE + e]; }
#pragma unroll
            for (int ni = 0; ni < 4; ni++) {
                int c0 = coff + ni * 8 + 2 * t;
                float bb0 = biasp ? biasp[c0] : 0.f;
                float bb1 = biasp ? biasp[c0 + 1] : 0.f;
                float v00 = acc[mi][ni][0] + bb0, v01 = acc[mi][ni][1] + bb1;
                float v10 = acc[mi][ni][2] + bb0, v11 = acc[mi][ni][3] + bb1;
                if (EPI == 1 || EPI == 4 || EPI == 5) {
                    v00 = fmaxf(v00, 0.f); v01 = fmaxf(v01, 0.f);
                    v10 = fmaxf(v10, 0.f); v11 = fmaxf(v11, 0.f);
                }
                if (EPI == 4) { v00 *= s0; v01 *= s0; v10 *= s1; v11 *= s1; }
                if (EPI == 1 || EPI == 2 || EPI == 4) {
                    v00 = rna_tf32(v00); v01 = rna_tf32(v01);
                    v10 = rna_tf32(v10); v11 = rna_tf32(v11);
                }
                Cp[(size_t)r0 * ldc + c0] = v00; Cp[(size_t)r0 * ldc + c0 + 1] = v01;
                Cp[(size_t)r1 * ldc + c0] = v10; Cp[(size_t)r1 * ldc + c0 + 1] = v11;
            }
        }
    }
}

// ---------------- launch ----------------
extern "C" void kernel_launch(void* const* d_in, const int* in_sizes, int n_in,
                              void* d_out, int out_size) {
    const float* state = (const float*)d_in[0];
    const float* act   = (const float*)d_in[1];
    const float* repW0 = (const float*)d_in[2];
    const float* repb0 = (const float*)d_in[3];
    const float* repW1 = (const float*)d_in[4];
    const float* repb1 = (const float*)d_in[5];
    const float* emb   = (const float*)d_in[6];
    const float* Wk0   = (const float*)d_in[7];
    const float* bk0   = (const float*)d_in[8];
    const float* Wk1   = (const float*)d_in[9];
    const float* bk1   = (const float*)d_in[10];
    const float* Wv0   = (const float*)d_in[11];
    const float* bv0   = (const float*)d_in[12];
    const float* Wv1   = (const float*)d_in[13];
    const float* bv1   = (const float*)d_in[14];
    const float* Wt0   = (const float*)d_in[15];
    const float* bt0   = (const float*)d_in[16];
    const float* Wt1   = (const float*)d_in[17];
    const float* bt1   = (const float*)d_in[18];
    const float* Wt2   = (const float*)d_in[19];
    const float* bt2   = (const float*)d_in[20];
    (void)in_sizes; (void)n_in;

    float *xp, *h0p, *repp, *gvp, *tinp, *t1p, *t2p;
    cudaGetSymbolAddress((void**)&xp, g_x);
    cudaGetSymbolAddress((void**)&h0p, g_h0);
    cudaGetSymbolAddress((void**)&repp, g_rep);
    cudaGetSymbolAddress((void**)&gvp, g_gv);
    cudaGetSymbolAddress((void**)&tinp, g_tin);
    cudaGetSymbolAddress((void**)&t1p, g_t1);
    cudaGetSymbolAddress((void**)&t2p, g_t2);

    prep_kernel<<<BB, 128>>>(state, act);
    wq_kernel<<<dim3(NE, NT), 256>>>(Wk1, bk1, emb);
    initlogits_kernel<<<(BB * NE) / 256, 256>>>();

    // h0 = relu(x @ W0 + b0)
    gemm_tf32<1><<<dim3(DREP / BN, BB / BM, 1), 256>>>(
        xp, XDIM, repW0, DREP, 0, h0p, DREP, 0, repb0, 0, XDIM);
    // rep = h0 @ W1 + b1   (rounded)
    gemm_tf32<2><<<dim3(DREP / BN, BB / BM, 1), 256>>>(
        h0p, DREP, repW1, DREP, 0, repp, DREP, 0, repb1, 0, DREP);
    // fused: logits += relu(rep @ Wk0[e] + bk0[e]) . wq[e,task,:]   (batched z=16)
    gemm_tf32<3><<<dim3(DH / BN, BB / BM, NE), 256>>>(
        repp, DREP, Wk0, DH, (long long)DREP * DH, nullptr, 0, 0, bk0, DH, DREP);

    softmax_kernel<<<BB / 256, 256>>>();

    // gv[b][e*DH+h] = attn[b,e] * relu(rep @ Wv0[e] + bv0[e])
    gemm_tf32<4><<<dim3(DH / BN, BB / BM, NE), 256>>>(
        repp, DREP, Wv0, DH, (long long)DREP * DH, gvp, NE * DH, DH, bv0, DH, DREP);
    // tower_in = gv @ Wv1_flat  (K = 16384)
    gemm_tf32<0><<<dim3(DKK / BN, BB / BM, 1), 256>>>(
        gvp, NE * DH, Wv1, DKK, 0, tinp, DKK, 0, nullptr, 0, NE * DH);
    mixbias_kernel<<<(BB * DKK) / 256, 256>>>(bv1);

    // tower
    gemm_tf32<1><<<dim3(512 / BN, BB / BM, 1), 256>>>(
        tinp, DKK, Wt0, 512, 0, t1p, 512, 0, bt0, 0, DKK);
    gemm_tf32<5><<<dim3(256 / BN, BB / BM, 1), 256>>>(
        t1p, 512, Wt1, 256, 0, t2p, 256, 0, bt1, 0, 512);

    finalize_kernel<<<BB / 8, 256>>>(Wt2, bt2, (float*)d_out, out_size);
}